// round 12
// baseline (speedup 1.0000x reference)
#include <cuda_runtime.h>

// Problem shape (fixed by dataset instance)
#define B_   8
#define H_   96
#define W_   320
#define HWp  (H_ * W_)            // 30720
#define NPIX (B_ * HWp)           // 245760
#define VOL_ELEMS (B_ * 45 * HWp) // 11059200
#define INTERVAL (4.0f / 7.0f)
#define G_VOL  960                // vol block slots (x2 pixels/thread = 1920 tiles)
#define G_DISP 240                // disp block slots (x2 iterations = 480 tiles)

struct Px { float c0, c1, c2; int J2lo, idx; };

__device__ __forceinline__ Px mkpx(int idx, float d)
{
    Px q; q.idx = idx;
    float fx = (float)(idx % W_);
    q.c0 = fminf(fmaxf(__fsub_rn(fx, d), 0.0f), 319.0f);
    q.c1 = fminf(fmaxf(__fsub_rn(__fmul_rn(fx, 0.5f),  __fmul_rn(d, 0.5f)),  0.0f), 159.0f);
    q.c2 = fminf(fmaxf(__fsub_rn(__fmul_rn(fx, 0.25f), __fmul_rn(d, 0.25f)), 0.0f), 79.0f);
    q.J2lo = max(0, (int)floorf(q.c2) - 4);
    return q;
}

__global__ void __launch_bounds__(128, 6)
pcv_kernel(const float* __restrict__ corr,
           const float* __restrict__ disp,
           float* __restrict__ out)
{
    int bid = blockIdx.x;
    int t   = threadIdx.x;

    // ---- Disp-writer blocks (interleaved 1-in-5; 2 tiles each): closed form ----
    if (bid % 5 == 4) {
        int dp = bid / 5;                           // [0, G_DISP)
        #pragma unroll
        for (int k = 0; k < 2; ++k) {
            int g  = (dp + G_DISP * k) * 128 + t;   // quad index in [0, NPIX/4)
            int x4 = g % (W_ / 4);
            int bh = g / (W_ / 4);
            int x  = 4 * x4;
            float4 d4 = *reinterpret_cast<const float4*>(disp + bh * W_ + x);
            int b = bh / H_;
            int h = bh - b * H_;
            float* dst = out + VOL_ELEMS + ((size_t)(b * 45) * H_ + h) * W_ + x;
            #pragma unroll
            for (int lv = 0; lv < 3; ++lv) {
                float inv = (lv == 0) ? 1.0f : (lv == 1) ? 0.5f : 0.25f;
                float4 dl;
                dl.x = __fmul_rn(d4.x, inv); dl.y = __fmul_rn(d4.y, inv);
                dl.z = __fmul_rn(d4.z, inv); dl.w = __fmul_rn(d4.w, inv);
                #pragma unroll
                for (int c = 0; c < 15; ++c) {
                    float kk = __fmul_rn((float)(c - 7), INTERVAL);
                    float4 v;
                    v.x = __fadd_rn(kk, dl.x); v.y = __fadd_rn(kk, dl.y);
                    v.z = __fadd_rn(kk, dl.z); v.w = __fadd_rn(kk, dl.w);
                    *reinterpret_cast<float4*>(dst + (size_t)(lv * 15 + c) * HWp) = v;
                }
            }
        }
        return;
    }

    // ---- Vol blocks (2 pixels/thread, software-pipelined gather) ----
    // Slot-major per-thread windows: element (slot, t) at [slot*128 + t].
    __shared__ float l0S[16 * 128];
    __shared__ float p1S[10 * 128];
    __shared__ float p2S[10 * 128];

    float* l0 = l0S + t;
    float* p1 = p1S + t;
    float* p2 = p2S + t;

    const float4* corr4 = reinterpret_cast<const float4*>(corr);

    int vbid = (bid / 5) * 4 + (bid % 5);           // [0, G_VOL)
    int idx0 = vbid * 128 + t;

    // Both disp loads issue up-front (independent); pixel-0 gather follows.
    float d0 = __ldg(disp + idx0);
    float d1 = __ldg(disp + idx0 + G_VOL * 128);
    Px cur = mkpx(idx0, d0);

    float4 vv[10];
    {
        const float4* r4 = corr4 + (size_t)idx0 * (W_ / 4);
        int n4 = min(79, (int)ceilf(cur.c2) + 4) - cur.J2lo;
        #pragma unroll
        for (int j = 0; j < 10; ++j)
            vv[j] = __ldcs(r4 + (cur.J2lo + min(j, n4)));
    }

    // e_s = floor(s * 4/7) — compile-time
    const int EL[8] = {0, 0, 1, 1, 2, 2, 3, 4};

    #pragma unroll
    for (int k = 0; k < 2; ++k) {
        // Derived indices for 'cur' (cheap recompute keeps the struct small).
        float F0 = floorf(cur.c0), F1 = floorf(cur.c1), F2 = floorf(cur.c2);
        int iF0 = (int)F0, iF1 = (int)F1;
        int J2lo = cur.J2lo;
        int J2hi = min(79, (int)ceilf(cur.c2) + 4);
        int J1lo = max(0, iF1 - 4);
        int K0   = max(0, iF0 - 4) >> 2;

        // ---- Scatter 'cur' windows into smem (consumes vv) ----
        #pragma unroll
        for (int jj = 0; jj < 10; ++jj) {
            float4 v = vv[jj];
            int q = J2lo + jj - K0;
            if ((unsigned)q < 4u) {
                l0[(4*q+0) * 128] = v.x; l0[(4*q+1) * 128] = v.y;
                l0[(4*q+2) * 128] = v.z; l0[(4*q+3) * 128] = v.w;
            }
            float s0 = __fmul_rn(__fadd_rn(v.x, v.y), 0.5f);
            float s1 = __fmul_rn(__fadd_rn(v.z, v.w), 0.5f);
            int slot = 2 * (J2lo + jj) - J1lo;
            if ((unsigned)slot       < 10u) p1[slot * 128]       = s0;
            if ((unsigned)(slot + 1) < 10u) p1[(slot + 1) * 128] = s1;
            p2[jj * 128] = __fmul_rn(__fadd_rn(s0, s1), 0.5f);
        }

        // ---- Prefetch pixel 1: its real gather flies during pixel-0 sampling ----
        Px nxt = cur;
        if (k == 0) {
            int idx1 = idx0 + G_VOL * 128;
            nxt = mkpx(idx1, d1);
            const float4* r4 = corr4 + (size_t)idx1 * (W_ / 4);
            int m4 = min(79, (int)ceilf(nxt.c2) + 4) - nxt.J2lo;
            #pragma unroll
            for (int j = 0; j < 10; ++j)
                vv[j] = __ldcs(r4 + (nxt.J2lo + min(j, m4)));
        }

        // ---- Sample 'cur' via register windows (R10 sampler) ----
        int x  = cur.idx % W_;
        int bh = cur.idx / W_;
        int b  = bh / H_;
        int h  = bh - b * H_;
        int volBase = (b * 45 * H_ + h) * W_ + x;
        float fx = (float)x;

        const float ctr[3]   = {cur.c0, cur.c1, cur.c2};
        const float Ffs[3]   = {F0, F1, F2};
        const float w1m1a[3] = {319.0f, 159.0f, 79.0f};
        const int   offA[3]  = { iF0 - 4 - 4 * K0, iF1 - 4 - J1lo, (int)F2 - 4 - J2lo };
        const int   top1     = min(9, 2 * J2hi + 1 - J1lo);

        #pragma unroll
        for (int lv = 0; lv < 3; ++lv) {
            const float* win = (lv == 0) ? l0 : (lv == 1) ? p1 : p2;
            int   off    = offA[lv];
            float Ff     = Ffs[lv];
            float center = ctr[lv];
            float w1m1   = w1m1a[lv];
            float inv    = (lv == 0) ? 1.0f : (lv == 1) ? 0.5f : 0.25f;

            // Register window: w[i] == level-window[F-4+i]; clamped slots only
            // feed zero-weight or guarded-off samples.
            float w[10];
            #pragma unroll
            for (int i = 0; i < 10; ++i) {
                int s = max(off + i, 0);
                if (lv == 1) s = min(s, top1);
                w[i] = win[s * 128];
            }

            float fm4  = __fsub_rn(Ff, 4.0f);
            float cm4  = __fsub_rn(center, 4.0f);
            float cp4  = __fadd_rn(center, 4.0f);
            float stdv = __fmul_rn(fx, inv);

            float* outL = out + volBase + lv * 15 * HWp;

            #pragma unroll
            for (int s8 = 0; s8 < 8; ++s8) {
                const int e = EL[s8];
                float offs = __fmul_rn((float)s8, INTERVAL);

                // LEFT: floor(lc) in {F-4+e, F-4+e+1}.
                float lc   = __fadd_rn(cm4, offs);
                float bnd0 = __fadd_rn(fm4, (float)e);
                float bnd1 = __fadd_rn(fm4, (float)(e + 1));
                bool  bl   = lc >= bnd1;
                float a    = bl ? w[e + 1] : w[e];
                float bb   = bl ? w[e + 2] : w[e + 1];
                float wt   = __fsub_rn(lc, bl ? bnd1 : bnd0);
                float v    = __fmaf_rn(wt, __fsub_rn(bb, a), a);
                outL[s8 * HWp] = (lc > 0.0f) ? v : 0.0f;

                // RIGHT: sample s -> channel 14-s.
                if (s8 < 7) {
                    float rc = __fsub_rn(cp4, offs);
                    float dn = __fsub_rn(stdv, rc);
                    float c  = fminf(rc, w1m1);
                    float r0 = __fadd_rn(Ff, (float)(3 - e));
                    float r1 = __fadd_rn(Ff, (float)(4 - e));
                    bool  br = c >= r1;
                    float ar  = br ? w[8 - e] : w[7 - e];
                    float bbr = br ? w[9 - e] : w[8 - e];
                    float wr  = __fsub_rn(c, br ? r1 : r0);
                    float vr  = __fmaf_rn(wr, __fsub_rn(bbr, ar), ar);
                    outL[(14 - s8) * HWp] = (dn > 0.0f && dn < w1m1) ? vr : 0.0f;
                }
            }
        }

        cur = nxt;
    }
}

extern "C" void kernel_launch(void* const* d_in, const int* in_sizes, int n_in,
                              void* d_out, int out_size)
{
    const float* corr = (const float*)d_in[0];   // cross_attention [8,96,320,320]
    const float* disp = (const float*)d_in[1];   // cur_disp [8,1,96,320]
    float* out = (float*)d_out;                  // [vol ; disps], each [8,45,96,320]
    pcv_kernel<<<G_VOL + G_DISP, 128>>>(corr, disp, out);
}

// round 13
// speedup vs baseline: 1.3616x; 1.3616x over previous
#include <cuda_runtime.h>

// Problem shape (fixed by dataset instance)
#define B_   8
#define H_   96
#define W_   320
#define HWp  (H_ * W_)            // 30720
#define NPIX (B_ * HWp)           // 245760
#define VOL_ELEMS (B_ * 45 * HWp) // 11059200
#define INTERVAL (4.0f / 7.0f)
#define NVOLB  1920               // vol blocks (NPIX/128)
#define NDISPB 480                // disp blocks (NPIX/4/128)

// Sample one pyramid level from a register window w[0..9] (w[i] = level[F-4+i]).
// Mirrors R10's proven numerics exactly.
__device__ __forceinline__ void sample_level(const float w[10],
                                             float Ff, float center, float w1m1,
                                             float stdv, float* __restrict__ outL)
{
    const int EL[8] = {0, 0, 1, 1, 2, 2, 3, 4};   // floor(s*4/7)
    float fm4 = __fsub_rn(Ff, 4.0f);
    float cm4 = __fsub_rn(center, 4.0f);
    float cp4 = __fadd_rn(center, 4.0f);

    #pragma unroll
    for (int s8 = 0; s8 < 8; ++s8) {
        const int e = EL[s8];
        float offs = __fmul_rn((float)s8, INTERVAL);

        // LEFT: floor(lc) in {F-4+e, F-4+e+1}; pick via exact float compare.
        float lc   = __fadd_rn(cm4, offs);
        float bnd0 = __fadd_rn(fm4, (float)e);
        float bnd1 = __fadd_rn(fm4, (float)(e + 1));
        bool  bl   = lc >= bnd1;
        float a    = bl ? w[e + 1] : w[e];
        float bb   = bl ? w[e + 2] : w[e + 1];
        float wt   = __fsub_rn(lc, bl ? bnd1 : bnd0);
        float v    = __fmaf_rn(wt, __fsub_rn(bb, a), a);
        outL[s8 * HWp] = (lc > 0.0f) ? v : 0.0f;

        // RIGHT: sample s -> channel 14-s; floor(c) in {F+3-e, F+4-e}.
        if (s8 < 7) {
            float rc = __fsub_rn(cp4, offs);
            float dn = __fsub_rn(stdv, rc);
            float c  = fminf(rc, w1m1);
            float r0 = __fadd_rn(Ff, (float)(3 - e));
            float r1 = __fadd_rn(Ff, (float)(4 - e));
            bool  br = c >= r1;
            float ar  = br ? w[8 - e] : w[7 - e];
            float bbr = br ? w[9 - e] : w[8 - e];
            float wr  = __fsub_rn(c, br ? r1 : r0);
            float vr  = __fmaf_rn(wr, __fsub_rn(bbr, ar), ar);
            outL[(14 - s8) * HWp] = (dn > 0.0f && dn < w1m1) ? vr : 0.0f;
        }
    }
}

__global__ void __launch_bounds__(128, 7)
pcv_kernel(const float* __restrict__ corr,
           const float* __restrict__ disp,
           float* __restrict__ out)
{
    int bid = blockIdx.x;
    int t   = threadIdx.x;

    // ---- Disp-writer blocks (interleaved 1-in-5): closed-form, float4 stores ----
    if (bid % 5 == 4) {
        int g  = (bid / 5) * 128 + t;          // quad index in [0, NPIX/4)
        int x4 = g % (W_ / 4);
        int bh = g / (W_ / 4);
        int x  = 4 * x4;
        float4 d4 = *reinterpret_cast<const float4*>(disp + bh * W_ + x);
        int b = bh / H_;
        int h = bh - b * H_;
        float* dst = out + VOL_ELEMS + ((size_t)(b * 45) * H_ + h) * W_ + x;
        #pragma unroll
        for (int lv = 0; lv < 3; ++lv) {
            float inv = (lv == 0) ? 1.0f : (lv == 1) ? 0.5f : 0.25f;
            float4 dl;
            dl.x = __fmul_rn(d4.x, inv); dl.y = __fmul_rn(d4.y, inv);
            dl.z = __fmul_rn(d4.z, inv); dl.w = __fmul_rn(d4.w, inv);
            #pragma unroll
            for (int c = 0; c < 15; ++c) {
                float kk = __fmul_rn((float)(c - 7), INTERVAL);
                float4 v;
                v.x = __fadd_rn(kk, dl.x); v.y = __fadd_rn(kk, dl.y);
                v.z = __fadd_rn(kk, dl.z); v.w = __fadd_rn(kk, dl.w);
                *reinterpret_cast<float4*>(dst + (size_t)(lv * 15 + c) * HWp) = v;
            }
        }
        return;
    }

    // ---- Vol blocks ----
    __shared__ float  p1S[10 * 128];        // level-1 window, bank-column
    __shared__ float  p2S[10 * 128];        // level-2 window, bank-column
    __shared__ float4 stageS[4 * 32 * 11];  // per-warp raw staging (stride 11 f4)
    // total static smem = 10240 + 10240 + 22528 = 32 KB exactly -> 7 blocks/SM

    int lane = t & 31;
    int warp = t >> 5;

    int vbid = (bid / 5) * 4 + (bid % 5);   // [0, 1920)
    int idx  = vbid * 128 + t;

    int x  = idx % W_;
    int bh = idx / W_;
    float d  = __ldg(disp + idx);
    float fx = (float)x;

    // centers per level: clip(x/2^i - d/2^i, 0, w1-1)
    float c0 = fminf(fmaxf(__fsub_rn(fx, d), 0.0f), 319.0f);
    float c1 = fminf(fmaxf(__fsub_rn(__fmul_rn(fx, 0.5f),  __fmul_rn(d, 0.5f)),  0.0f), 159.0f);
    float c2 = fminf(fmaxf(__fsub_rn(__fmul_rn(fx, 0.25f), __fmul_rn(d, 0.25f)), 0.0f), 79.0f);

    float F0 = floorf(c0), F1 = floorf(c1), F2 = floorf(c2);
    int iF0 = (int)F0, iF1 = (int)F1, iF2 = (int)F2;

    int J2lo = max(0, iF2 - 4);
    int J2hi = min(79, (int)ceilf(c2) + 4);
    int n4   = J2hi - J2lo;                 // 4..9
    int J1lo = max(0, iF1 - 4);
    int R0   = 4 * J2lo;

    // ---- Cooperative warp gather: lanes fetch consecutive float4s of the
    // same pixel's window (contiguous lines) instead of one float4 from 32
    // different rows. (pixel, j) = (lin/10, lin%10); per-target params via shfl.
    float4* st = stageS + warp * (32 * 11);
    unsigned pk = (unsigned)J2lo | ((unsigned)n4 << 8);
    int pix0 = vbid * 128 + (t & ~31);      // global pixel of lane 0 in this warp
    const float4* corr4 = reinterpret_cast<const float4*>(corr);

    #pragma unroll
    for (int it = 0; it < 10; ++it) {
        int lin = it * 32 + lane;           // 0..319
        int p   = lin / 10;                 // pixel within warp
        int j   = lin - p * 10;             // float4 slot
        unsigned pkp = __shfl_sync(0xffffffffu, pk, p);
        int J2p = (int)(pkp & 0xffu);
        int n4p = (int)(pkp >> 8);
        const float4* r4 = corr4 + (size_t)(pix0 + p) * (W_ / 4);
        st[p * 11 + j] = __ldcs(r4 + (J2p + min(j, n4p)));
    }
    __syncwarp();

    // ---- Read back own raw window; scatter p1/p2 windows (bank-column) ----
    float* p1 = p1S + t;
    float* p2 = p2S + t;
    #pragma unroll
    for (int jj = 0; jj < 10; ++jj) {
        float4 v = st[lane * 11 + jj];
        float s0 = __fmul_rn(__fadd_rn(v.x, v.y), 0.5f);
        float s1 = __fmul_rn(__fadd_rn(v.z, v.w), 0.5f);
        int slot = 2 * (J2lo + jj) - J1lo;
        if ((unsigned)slot       < 10u) p1[slot * 128]       = s0;
        if ((unsigned)(slot + 1) < 10u) p1[(slot + 1) * 128] = s1;
        p2[jj * 128] = __fmul_rn(__fadd_rn(s0, s1), 0.5f);
    }

    int b = bh / H_;
    int h = bh - b * H_;
    int volBase = (b * 45 * H_ + h) * W_ + x;

    // ---- Register windows per level ----
    // Level 0 straight from staged raw floats (clamped to valid extent; clamped
    // slots only feed zero-weight or guarded-off samples).
    const float* stf = reinterpret_cast<const float*>(st) + lane * 44;
    int o0   = iF0 - 4 - R0;
    int rmax = 4 * n4 + 3;
    float w0_[10];
    #pragma unroll
    for (int i = 0; i < 10; ++i)
        w0_[i] = stf[min(max(o0 + i, 0), rmax)];

    int off1 = iF1 - 4 - J1lo;              // in [-4, 0]
    int top1 = min(9, 2 * J2hi + 1 - J1lo);
    float w1_[10];
    #pragma unroll
    for (int i = 0; i < 10; ++i)
        w1_[i] = p1[min(max(off1 + i, 0), top1) * 128];

    int off2 = iF2 - 4 - J2lo;              // in [-4, 0]
    float w2_[10];
    #pragma unroll
    for (int i = 0; i < 10; ++i)
        w2_[i] = p2[max(off2 + i, 0) * 128];

    // ---- Sample all levels ----
    sample_level(w0_, F0, c0, 319.0f, fx,                      out + volBase);
    sample_level(w1_, F1, c1, 159.0f, __fmul_rn(fx, 0.5f),     out + volBase + 15 * HWp);
    sample_level(w2_, F2, c2, 79.0f,  __fmul_rn(fx, 0.25f),    out + volBase + 30 * HWp);
}

extern "C" void kernel_launch(void* const* d_in, const int* in_sizes, int n_in,
                              void* d_out, int out_size)
{
    const float* corr = (const float*)d_in[0];   // cross_attention [8,96,320,320]
    const float* disp = (const float*)d_in[1];   // cur_disp [8,1,96,320]
    float* out = (float*)d_out;                  // [vol ; disps], each [8,45,96,320]
    pcv_kernel<<<NVOLB + NDISPB, 128>>>(corr, disp, out);
}

// round 14
// speedup vs baseline: 1.6442x; 1.2076x over previous
#include <cuda_runtime.h>

// Problem shape (fixed by dataset instance)
#define B_   8
#define H_   96
#define W_   320
#define HWp  (H_ * W_)            // 30720
#define NPIX (B_ * HWp)           // 245760
#define VOL_ELEMS (B_ * 45 * HWp) // 11059200
#define INTERVAL (4.0f / 7.0f)
#define NVOLB  1920               // vol blocks (NPIX/128)
#define NDISPB 480                // disp blocks (NPIX/4/128)

// Sample one pyramid level from a register window w[0..9] (w[i] = level[F-4+i]).
// R10's proven numerics, unchanged.
__device__ __forceinline__ void sample_level(const float w[10],
                                             float Ff, float center, float w1m1,
                                             float stdv, float* __restrict__ outL)
{
    const int EL[8] = {0, 0, 1, 1, 2, 2, 3, 4};   // floor(s*4/7)
    float fm4 = __fsub_rn(Ff, 4.0f);
    float cm4 = __fsub_rn(center, 4.0f);
    float cp4 = __fadd_rn(center, 4.0f);

    #pragma unroll
    for (int s8 = 0; s8 < 8; ++s8) {
        const int e = EL[s8];
        float offs = __fmul_rn((float)s8, INTERVAL);

        // LEFT: floor(lc) in {F-4+e, F-4+e+1}; pick via exact float compare.
        float lc   = __fadd_rn(cm4, offs);
        float bnd0 = __fadd_rn(fm4, (float)e);
        float bnd1 = __fadd_rn(fm4, (float)(e + 1));
        bool  bl   = lc >= bnd1;
        float a    = bl ? w[e + 1] : w[e];
        float bb   = bl ? w[e + 2] : w[e + 1];
        float wt   = __fsub_rn(lc, bl ? bnd1 : bnd0);
        float v    = __fmaf_rn(wt, __fsub_rn(bb, a), a);
        outL[s8 * HWp] = (lc > 0.0f) ? v : 0.0f;

        // RIGHT: sample s -> channel 14-s; floor(c) in {F+3-e, F+4-e}.
        if (s8 < 7) {
            float rc = __fsub_rn(cp4, offs);
            float dn = __fsub_rn(stdv, rc);
            float c  = fminf(rc, w1m1);
            float r0 = __fadd_rn(Ff, (float)(3 - e));
            float r1 = __fadd_rn(Ff, (float)(4 - e));
            bool  br = c >= r1;
            float ar  = br ? w[8 - e] : w[7 - e];
            float bbr = br ? w[9 - e] : w[8 - e];
            float wr  = __fsub_rn(c, br ? r1 : r0);
            float vr  = __fmaf_rn(wr, __fsub_rn(bbr, ar), ar);
            outL[(14 - s8) * HWp] = (dn > 0.0f && dn < w1m1) ? vr : 0.0f;
        }
    }
}

__global__ void __launch_bounds__(128, 8)
pcv_kernel(const float* __restrict__ corr,
           const float* __restrict__ disp,
           float* __restrict__ out)
{
    int bid = blockIdx.x;
    int t   = threadIdx.x;

    // ---- Disp-writer blocks (interleaved 1-in-5): closed-form, float4 stores ----
    if (bid % 5 == 4) {
        int g  = (bid / 5) * 128 + t;          // quad index in [0, NPIX/4)
        int x4 = g % (W_ / 4);
        int bh = g / (W_ / 4);
        int x  = 4 * x4;
        float4 d4 = *reinterpret_cast<const float4*>(disp + bh * W_ + x);
        int b = bh / H_;
        int h = bh - b * H_;
        float* dst = out + VOL_ELEMS + ((size_t)(b * 45) * H_ + h) * W_ + x;
        #pragma unroll
        for (int lv = 0; lv < 3; ++lv) {
            float inv = (lv == 0) ? 1.0f : (lv == 1) ? 0.5f : 0.25f;
            float4 dl;
            dl.x = __fmul_rn(d4.x, inv); dl.y = __fmul_rn(d4.y, inv);
            dl.z = __fmul_rn(d4.z, inv); dl.w = __fmul_rn(d4.w, inv);
            #pragma unroll
            for (int c = 0; c < 15; ++c) {
                float kk = __fmul_rn((float)(c - 7), INTERVAL);
                float4 v;
                v.x = __fadd_rn(kk, dl.x); v.y = __fadd_rn(kk, dl.y);
                v.z = __fadd_rn(kk, dl.z); v.w = __fadd_rn(kk, dl.w);
                *reinterpret_cast<float4*>(dst + (size_t)(lv * 15 + c) * HWp) = v;
            }
        }
        return;
    }

    // ---- Vol blocks ----
    // Single staging buffer: 45-float stride per pixel (gcd(45,32)=1 ->
    // conflict-free scalar readback at uniform offsets). 22.5 KB -> 8 blocks/SM.
    __shared__ float stageS[128 * 45];

    int lane = t & 31;
    int warp = t >> 5;

    int vbid = (bid / 5) * 4 + (bid % 5);   // [0, 1920)
    int idx  = vbid * 128 + t;

    int x  = idx % W_;
    int bh = idx / W_;
    float d  = __ldg(disp + idx);
    float fx = (float)x;

    // centers per level: clip(x/2^i - d/2^i, 0, w1-1)
    float c0 = fminf(fmaxf(__fsub_rn(fx, d), 0.0f), 319.0f);
    float c1 = fminf(fmaxf(__fsub_rn(__fmul_rn(fx, 0.5f),  __fmul_rn(d, 0.5f)),  0.0f), 159.0f);
    float c2 = fminf(fmaxf(__fsub_rn(__fmul_rn(fx, 0.25f), __fmul_rn(d, 0.25f)), 0.0f), 79.0f);

    float F0 = floorf(c0), F1 = floorf(c1), F2 = floorf(c2);
    int iF0 = (int)F0, iF1 = (int)F1, iF2 = (int)F2;

    int J2lo = max(0, iF2 - 4);
    int J2hi = min(79, (int)ceilf(c2) + 4);
    int n4   = J2hi - J2lo;                 // 4..9
    int J1lo = max(0, iF1 - 4);
    int R0   = 4 * J2lo;

    // ---- Cooperative warp gather: lanes fetch consecutive float4s of the same
    // pixel's window (contiguous lines; ~7 lines/instr instead of 32).
    // (pixel, j) = (lin/10, lin%10); per-target params via shfl. All 10 slots of
    // every pixel get written (clamped source) -> staging is always finite.
    float* stw = stageS + warp * (32 * 45);
    unsigned pk = (unsigned)J2lo | ((unsigned)n4 << 8);
    int pix0 = vbid * 128 + (t & ~31);
    const float4* corr4 = reinterpret_cast<const float4*>(corr);

    #pragma unroll
    for (int it = 0; it < 10; ++it) {
        int lin = it * 32 + lane;           // 0..319
        int p   = lin / 10;
        int j   = lin - p * 10;
        unsigned pkp = __shfl_sync(0xffffffffu, pk, p);
        int J2p = (int)(pkp & 0xffu);
        int n4p = (int)(pkp >> 8);
        float4 v = __ldcs(corr4 + (size_t)(pix0 + p) * (W_ / 4) + (J2p + min(j, n4p)));
        float* dst = stw + p * 45 + 4 * j;
        dst[0] = v.x; dst[1] = v.y; dst[2] = v.z; dst[3] = v.w;
    }
    __syncwarp();

    const float* stf = stw + lane * 45;     // this thread's 40 raw floats

    int b = bh / H_;
    int h = bh - b * H_;
    int volBase = (b * 45 * H_ + h) * W_ + x;

    // ---- Level 0: window straight from staged raw ----
    {
        int o0 = iF0 - 4 - R0;              // valid reads within true data (proof R4-R10)
        float w0_[10];
        #pragma unroll
        for (int i = 0; i < 10; ++i)
            w0_[i] = stf[min(max(o0 + i, 0), 39)];
        sample_level(w0_, F0, c0, 319.0f, fx, out + volBase);
    }

    // ---- Level 1: pool pairs on the fly (identical arithmetic to prior rounds) ----
    {
        int o1 = 2 * (iF1 - 4) - R0;        // even; pairs (u, u+1)
        float w1_[10];
        #pragma unroll
        for (int i = 0; i < 10; ++i) {
            int u = min(max(o1 + 2 * i, 0), 38);
            w1_[i] = __fmul_rn(__fadd_rn(stf[u], stf[u + 1]), 0.5f);
        }
        sample_level(w1_, F1, c1, 159.0f, __fmul_rn(fx, 0.5f), out + volBase + 15 * HWp);
    }

    // ---- Level 2: pairwise pool of 4 raw floats per slot ----
    {
        int o2 = iF2 - 4 - J2lo;            // in [-4, 0]
        float w2_[10];
        #pragma unroll
        for (int i = 0; i < 10; ++i) {
            int gg = max(o2 + i, 0);        // <= 9 always
            float s0 = __fmul_rn(__fadd_rn(stf[4*gg+0], stf[4*gg+1]), 0.5f);
            float s1 = __fmul_rn(__fadd_rn(stf[4*gg+2], stf[4*gg+3]), 0.5f);
            w2_[i] = __fmul_rn(__fadd_rn(s0, s1), 0.5f);
        }
        sample_level(w2_, F2, c2, 79.0f, __fmul_rn(fx, 0.25f), out + volBase + 30 * HWp);
    }
}

extern "C" void kernel_launch(void* const* d_in, const int* in_sizes, int n_in,
                              void* d_out, int out_size)
{
    const float* corr = (const float*)d_in[0];   // cross_attention [8,96,320,320]
    const float* disp = (const float*)d_in[1];   // cur_disp [8,1,96,320]
    float* out = (float*)d_out;                  // [vol ; disps], each [8,45,96,320]
    pcv_kernel<<<NVOLB + NDISPB, 128>>>(corr, disp, out);
}